// round 13
// baseline (speedup 1.0000x reference)
#include <cuda_runtime.h>
#include <cuda_fp16.h>
#include <cstdint>

// PIPNet fused gather + MLP via mma.sync (HMMA) single-fp16.
//   out[p] = relu(concat(g1[il[p]], g2[ir[p]]) @ W1^T + b1) @ W2^T + b2
//
// R12: R11 was overlap-limited (no pipe >50%, occ 24% at 2 CTAs/SM).
// Force 3 CTAs/SM via __launch_bounds__(256,3) (85-reg cap). Mainloop
// restructured for minimal live registers: each B uint4 is consumed by its
// 4 MMAs immediately after the load, so peak pressure is
// acc(64)+af(8)+vb(4)+bases (~84) -- fits without mainloop spills.

#define MTILE 128
#define NTHREADS 256

// smem layout (bytes): A tile 128x128 fp16 (rows 256B, swizzled 16B chunks).
#define SM_A    0
#define SM_B1   32768
#define SM_W2   33280
#define SM_RED  33792
#define SMEM_TOTAL (33792 + 1024 + 128)

// W1 fp16 fragment buffer: [nb(2)][ks(8)][pr(4)][lane(32)][reg(4)] u32 = 32KB.
__device__ uint32_t g_Wfrag[2 * 8 * 4 * 32 * 4];

static __device__ __forceinline__ uint32_t smem_u32(const void* p) {
    uint32_t a;
    asm("{ .reg .u64 t; cvta.to.shared.u64 t, %1; cvt.u32.u64 %0, t; }"
        : "=r"(a) : "l"(p));
    return a;
}

static __device__ __forceinline__ uint32_t tile_off(int row, int chunk) {
    return (uint32_t)row * 256u + (uint32_t)((chunk ^ (row & 7)) * 16);
}

static __device__ __forceinline__ void ldsm_x4(uint32_t* r, uint32_t addr) {
    asm volatile("ldmatrix.sync.aligned.m8n8.x4.shared.b16 {%0,%1,%2,%3}, [%4];"
                 : "=r"(r[0]), "=r"(r[1]), "=r"(r[2]), "=r"(r[3]) : "r"(addr));
}
static __device__ __forceinline__ void mma_f16(float* c, const uint32_t* a,
                                               uint32_t b0, uint32_t b1) {
    asm volatile("mma.sync.aligned.m16n8k16.row.col.f32.f16.f16.f32 "
                 "{%0,%1,%2,%3}, {%4,%5,%6,%7}, {%8,%9}, {%0,%1,%2,%3};"
                 : "+f"(c[0]), "+f"(c[1]), "+f"(c[2]), "+f"(c[3])
                 : "r"(a[0]), "r"(a[1]), "r"(a[2]), "r"(a[3]), "r"(b0), "r"(b1));
}

static __device__ __forceinline__ uint32_t pack_h2(__half a, __half b) {
    __half2 h = __halves2half2(a, b);
    return *(uint32_t*)&h;
}

// ---- Prep: write W1's fp16 mma B-fragments in fragment order ----
// NON-trans ldmatrix x4 reg j at lane l holds the f16x2 pair
// W1h[n][k], W1h[n][k+1] with
//   n = nb*64 + pr*16 + (j>>1)*8 + (l>>2),  k = ks*16 + (j&1)*8 + 2*(l&3).
__global__ void pipnet_prep_wfrag(const float* __restrict__ W1) {
    int flat = blockIdx.x * blockDim.x + threadIdx.x;   // 8192 entries
    if (flat >= 8192) return;
    int j  = flat & 3;
    int l  = (flat >> 2) & 31;
    int pr = (flat >> 7) & 3;
    int ks = (flat >> 9) & 7;
    int nb = (flat >> 12) & 1;
    int n = nb * 64 + pr * 16 + ((j >> 1) << 3) + (l >> 2);
    int k = ks * 16 + ((j & 1) << 3) + 2 * (l & 3);
    g_Wfrag[flat] = pack_h2(__float2half_rn(W1[n * 128 + k]),
                            __float2half_rn(W1[n * 128 + k + 1]));
}

__global__ __launch_bounds__(NTHREADS, 3)
void pipnet_hmma_kernel(const float* __restrict__ g1,
                        const float* __restrict__ g2,
                        const int* __restrict__ idxL,
                        const int* __restrict__ idxR,
                        const float* __restrict__ b1,
                        const float* __restrict__ W2,
                        const float* __restrict__ b2,
                        float* __restrict__ out,
                        int P, int Nnodes)
{
    extern __shared__ char smem[];
    const uint32_t sbase = smem_u32(smem);
    const int tid = threadIdx.x;
    const int wid = tid >> 5;
    const int lid = tid & 31;
    const long long base = (long long)blockIdx.x * MTILE;

    // ---- Stage b1 / W2 ----
    if (tid < 128) {
        *(float*)(smem + SM_B1 + tid * 4) = b1[tid];
        *(float*)(smem + SM_W2 + tid * 4) = W2[tid];
    }

    // ---- Coalesced gather: 16 lanes per node row, single fp16 ----
    // 256 row-halves: rh in [0,256), r = rh & 127 (pair row), h = rh >> 7.
    {
        const int lane_in = lid & 15;       // float4 position within the row
        #pragma unroll
        for (int i = 0; i < 16; ++i) {
            int rh = wid * 32 + i * 2 + (lid >> 4);
            int r = rh & 127;
            int h = rh >> 7;
            long long pair = base + r;
            if (pair >= P) pair = P - 1;
            int srcRow = h ? idxR[pair] : idxL[pair];
            if (srcRow < 0) srcRow = 0;
            if (srcRow >= Nnodes) srcRow = Nnodes - 1;
            const float4* src =
                (const float4*)((h ? g2 : g1) + (long long)srcRow * 64);
            float4 v = src[lane_in];
            uint2 hv = make_uint2(pack_h2(__float2half_rn(v.x), __float2half_rn(v.y)),
                                  pack_h2(__float2half_rn(v.z), __float2half_rn(v.w)));
            uint32_t off = tile_off(r, h * 8 + (lane_in >> 1)) + (lane_in & 1) * 8;
            *(uint2*)(smem + SM_A + off) = hv;
        }
    }
    __syncthreads();

    // ---- HMMA mainloop: warp = 32m x 64n ----
    const int m_base = (wid >> 1) * 32;
    const int nb = wid & 1;
    const int n_base = nb * 64;
    const int gl = lid & 7;
    const int grp = lid >> 3;

    float acc[2][8][4];
    #pragma unroll
    for (int mt = 0; mt < 2; ++mt)
        #pragma unroll
        for (int c = 0; c < 8; ++c)
            #pragma unroll
            for (int q = 0; q < 4; ++q) acc[mt][c][q] = 0.f;

    const uint32_t aT = sbase + SM_A;
    const uint4* __restrict__ Wf = (const uint4*)g_Wfrag;

    #pragma unroll
    for (int ks = 0; ks < 8; ++ks) {
        int kc = ks * 2;
        // A frags: 2 subtiles of 16 rows (2 LDSM.x4)
        uint32_t af0[4], af1[4];
        {
            int row0 = m_base + (grp & 1) * 8 + gl;
            ldsm_x4(af0, aT + tile_off(row0, kc + (grp >> 1)));
            ldsm_x4(af1, aT + tile_off(row0 + 16, kc + (grp >> 1)));
        }
        // B frags: one uint4 per pr, consumed immediately (min live regs)
        const uint4* wk = Wf + ((nb * 8 + ks) * 4) * 32 + lid;
        #pragma unroll
        for (int pr = 0; pr < 4; ++pr) {
            uint4 vb = wk[pr * 32];
            mma_f16(acc[0][pr * 2],     af0, vb.x, vb.y);
            mma_f16(acc[0][pr * 2 + 1], af0, vb.z, vb.w);
            mma_f16(acc[1][pr * 2],     af1, vb.x, vb.y);
            mma_f16(acc[1][pr * 2 + 1], af1, vb.z, vb.w);
        }
    }

    // ---- Epilogue: bias + ReLU + W2 dot from accumulators ----
    const float* s_b1 = (const float*)(smem + SM_B1);
    const float* s_w2 = (const float*)(smem + SM_W2);
    float* red = (float*)(smem + SM_RED);
    const int q2 = (lid & 3) * 2;

    #pragma unroll
    for (int mt = 0; mt < 2; ++mt) {
        float pa = 0.f, pb = 0.f;   // rows m_base+mt*16+(lid>>2) and +8
        #pragma unroll
        for (int c = 0; c < 8; ++c) {
            int n = n_base + c * 8 + q2;
            float b0 = s_b1[n], b1x = s_b1[n + 1];
            float w0 = s_w2[n], w1x = s_w2[n + 1];
            pa += fmaxf(acc[mt][c][0] + b0, 0.f) * w0
                + fmaxf(acc[mt][c][1] + b1x, 0.f) * w1x;
            pb += fmaxf(acc[mt][c][2] + b0, 0.f) * w0
                + fmaxf(acc[mt][c][3] + b1x, 0.f) * w1x;
        }
        pa += __shfl_xor_sync(0xffffffffu, pa, 1);
        pa += __shfl_xor_sync(0xffffffffu, pa, 2);
        pb += __shfl_xor_sync(0xffffffffu, pb, 1);
        pb += __shfl_xor_sync(0xffffffffu, pb, 2);
        if ((lid & 3) == 0) {
            int ra = m_base + mt * 16 + (lid >> 2);
            red[ra * 2 + nb] = pa;
            red[(ra + 8) * 2 + nb] = pb;
        }
    }
    __syncthreads();

    if (tid < MTILE) {
        float s = red[tid * 2] + red[tid * 2 + 1] + b2[0];
        long long p = base + tid;
        if (p < P) out[p] = s;
    }
}

extern "C" void kernel_launch(void* const* d_in, const int* in_sizes, int n_in,
                              void* d_out, int out_size) {
    const float* g1  = (const float*)d_in[0];   // graph1_x [N,64]
    const float* g2  = (const float*)d_in[1];   // graph2_x [N,64]
    const int*   il  = (const int*)d_in[2];     // idx_left  [P] int32
    const int*   ir  = (const int*)d_in[3];     // idx_right [P] int32
    const float* W1  = (const float*)d_in[4];   // [128,128]
    const float* b1  = (const float*)d_in[5];   // [128]
    const float* W2  = (const float*)d_in[6];   // [1,128]
    const float* b2  = (const float*)d_in[7];   // [1]
    float*       out = (float*)d_out;           // [P,1]

    int P = in_sizes[2];
    int Nnodes = in_sizes[0] / 64;
    int grid = (P + MTILE - 1) / MTILE;

    pipnet_prep_wfrag<<<32, 256>>>(W1);

    cudaFuncSetAttribute(pipnet_hmma_kernel,
                         cudaFuncAttributeMaxDynamicSharedMemorySize, SMEM_TOTAL);
    pipnet_hmma_kernel<<<grid, NTHREADS, SMEM_TOTAL>>>(
        g1, g2, il, ir, b1, W2, b2, out, P, Nnodes);
}

// round 14
// speedup vs baseline: 1.1652x; 1.1652x over previous
#include <cuda_runtime.h>
#include <cuda_fp16.h>
#include <cstdint>

// PIPNet fused gather + MLP via mma.sync (HMMA) single-fp16.
//   out[p] = relu(concat(g1[il[p]], g2[ir[p]]) @ W1^T + b1) @ W2^T + b2
//
// R13: R12's 85-reg cap spilled (regs=80, L2 44%) -> reverted to 128-reg /
// 2 CTAs/SM operating point. R11's residual gap (no pipe >50%) is gather/MMA
// serialization, so: ping-pong warp-group specialization. 8 warps = 2 groups
// of 4; in phase p, group (p&1) gathers tile T_p into buf(p&1) while the
// other group computes T_{p-1} from the other buf. Tile = 64 pairs; compute
// warp shape identical to R11 (32m x 64n, acc 64 regs, B frags via LDG).

#define NTHREADS 256
#define GRID_CTAS 1536

// smem layout (bytes): two 64x128 fp16 A buffers (rows 256B, swizzled chunks).
#define SM_A0   0
#define SM_A1   16384
#define SM_B1   32768
#define SM_W2   33280
#define SM_RED  33792
#define SMEM_TOTAL (33792 + 512 + 128)

// W1 fp16 fragment buffer: [nb(2)][ks(8)][pr(4)][lane(32)][reg(4)] u32 = 32KB.
__device__ uint32_t g_Wfrag[2 * 8 * 4 * 32 * 4];

static __device__ __forceinline__ uint32_t smem_u32(const void* p) {
    uint32_t a;
    asm("{ .reg .u64 t; cvta.to.shared.u64 t, %1; cvt.u32.u64 %0, t; }"
        : "=r"(a) : "l"(p));
    return a;
}

static __device__ __forceinline__ uint32_t tile_off(int row, int chunk) {
    return (uint32_t)row * 256u + (uint32_t)((chunk ^ (row & 7)) * 16);
}

static __device__ __forceinline__ void ldsm_x4(uint32_t* r, uint32_t addr) {
    asm volatile("ldmatrix.sync.aligned.m8n8.x4.shared.b16 {%0,%1,%2,%3}, [%4];"
                 : "=r"(r[0]), "=r"(r[1]), "=r"(r[2]), "=r"(r[3]) : "r"(addr));
}
static __device__ __forceinline__ void mma_f16(float* c, const uint32_t* a,
                                               uint32_t b0, uint32_t b1) {
    asm volatile("mma.sync.aligned.m16n8k16.row.col.f32.f16.f16.f32 "
                 "{%0,%1,%2,%3}, {%4,%5,%6,%7}, {%8,%9}, {%0,%1,%2,%3};"
                 : "+f"(c[0]), "+f"(c[1]), "+f"(c[2]), "+f"(c[3])
                 : "r"(a[0]), "r"(a[1]), "r"(a[2]), "r"(a[3]), "r"(b0), "r"(b1));
}

static __device__ __forceinline__ uint32_t pack_h2(__half a, __half b) {
    __half2 h = __halves2half2(a, b);
    return *(uint32_t*)&h;
}

// ---- Prep: write W1's fp16 mma B-fragments in fragment order ----
// NON-trans ldmatrix x4 reg j at lane l holds the f16x2 pair
// W1h[n][k], W1h[n][k+1] with
//   n = nb*64 + pr*16 + (j>>1)*8 + (l>>2),  k = ks*16 + (j&1)*8 + 2*(l&3).
__global__ void pipnet_prep_wfrag(const float* __restrict__ W1) {
    int flat = blockIdx.x * blockDim.x + threadIdx.x;   // 8192 entries
    if (flat >= 8192) return;
    int j  = flat & 3;
    int l  = (flat >> 2) & 31;
    int pr = (flat >> 7) & 3;
    int ks = (flat >> 9) & 7;
    int nb = (flat >> 12) & 1;
    int n = nb * 64 + pr * 16 + ((j >> 1) << 3) + (l >> 2);
    int k = ks * 16 + ((j & 1) << 3) + 2 * (l & 3);
    g_Wfrag[flat] = pack_h2(__float2half_rn(W1[n * 128 + k]),
                            __float2half_rn(W1[n * 128 + k + 1]));
}

__global__ __launch_bounds__(NTHREADS, 2)
void pipnet_hmma_kernel(const float* __restrict__ g1,
                        const float* __restrict__ g2,
                        const int* __restrict__ idxL,
                        const int* __restrict__ idxR,
                        const float* __restrict__ b1,
                        const float* __restrict__ W2,
                        const float* __restrict__ b2,
                        float* __restrict__ out,
                        int P, int Nnodes)
{
    extern __shared__ char smem[];
    const uint32_t sbase = smem_u32(smem);
    const int tid = threadIdx.x;
    const int wid = tid >> 5;
    const int lid = tid & 31;
    const int grpid = wid >> 2;         // warp group: 0 (warps 0-3), 1 (4-7)
    const int wg = wid & 3;             // warp within group

    const int numTiles = (P + 63) >> 6;

    // ---- Stage b1 / W2 ----
    if (tid < 128) {
        *(float*)(smem + SM_B1 + tid * 4) = b1[tid];
        *(float*)(smem + SM_W2 + tid * 4) = W2[tid];
    }
    const float b2v = b2[0];
    __syncthreads();

    // gather role constants
    const int lane_in = lid & 15;       // float4 slot within a node row
    // compute role constants (R11 shape on a 64-row tile)
    const int m_base = (wg >> 1) * 32;
    const int nb = wg & 1;
    const int n_base = nb * 64;
    const int gl = lid & 7;
    const int grp = lid >> 3;

    const uint4* __restrict__ Wf = (const uint4*)g_Wfrag;
    const float* s_b1 = (const float*)(smem + SM_B1);
    const float* s_w2 = (const float*)(smem + SM_W2);
    float* red = (float*)(smem + SM_RED);

    for (int p = 0; ; ++p) {
        long long tg = (long long)blockIdx.x + (long long)p * gridDim.x;
        long long tc = tg - gridDim.x;              // tile computed this phase
        bool any_gather  = (tg < numTiles);
        bool any_compute = (p >= 1) && (tc < numTiles);
        if (!any_gather && !any_compute) break;

        if ((p & 1) == grpid) {
            // ---- GATHER group: tile tg -> buf (p&1) ----
            if (any_gather) {
                char* buf = smem + ((p & 1) ? SM_A1 : SM_A0);
                #pragma unroll
                for (int i = 0; i < 16; ++i) {
                    int rh = wg * 32 + i * 2 + (lid >> 4);   // 0..127
                    int r = rh & 63;
                    int h = rh >> 6;
                    long long pair = tg * 64 + r;
                    if (pair >= P) pair = P - 1;
                    int srcRow = h ? idxR[pair] : idxL[pair];
                    if (srcRow < 0) srcRow = 0;
                    if (srcRow >= Nnodes) srcRow = Nnodes - 1;
                    const float4* src =
                        (const float4*)((h ? g2 : g1) + (long long)srcRow * 64);
                    float4 v = src[lane_in];
                    uint2 hv = make_uint2(
                        pack_h2(__float2half_rn(v.x), __float2half_rn(v.y)),
                        pack_h2(__float2half_rn(v.z), __float2half_rn(v.w)));
                    uint32_t off = tile_off(r, h * 8 + (lane_in >> 1))
                                 + (lane_in & 1) * 8;
                    *(uint2*)(buf + off) = hv;
                }
            }
        } else {
            // ---- COMPUTE group: tile tc from buf ((p-1)&1) ----
            if (any_compute) {
                const uint32_t aT = sbase + (((p ^ 1) & 1) ? SM_A1 : SM_A0);
                float acc[2][8][4];
                #pragma unroll
                for (int mt = 0; mt < 2; ++mt)
                    #pragma unroll
                    for (int c = 0; c < 8; ++c)
                        #pragma unroll
                        for (int q = 0; q < 4; ++q) acc[mt][c][q] = 0.f;

                #pragma unroll
                for (int ks = 0; ks < 8; ++ks) {
                    int kc = ks * 2;
                    uint32_t af0[4], af1[4];
                    int row0 = m_base + (grp & 1) * 8 + gl;
                    ldsm_x4(af0, aT + tile_off(row0, kc + (grp >> 1)));
                    ldsm_x4(af1, aT + tile_off(row0 + 16, kc + (grp >> 1)));
                    const uint4* wk = Wf + ((nb * 8 + ks) * 4) * 32 + lid;
                    #pragma unroll
                    for (int pr = 0; pr < 4; ++pr) {
                        uint4 vb = wk[pr * 32];
                        mma_f16(acc[0][pr * 2],     af0, vb.x, vb.y);
                        mma_f16(acc[0][pr * 2 + 1], af0, vb.z, vb.w);
                        mma_f16(acc[1][pr * 2],     af1, vb.x, vb.y);
                        mma_f16(acc[1][pr * 2 + 1], af1, vb.z, vb.w);
                    }
                }

                // epilogue: bias + ReLU + W2 dot, quad reduce, stage partials
                const int q2 = (lid & 3) * 2;
                #pragma unroll
                for (int mt = 0; mt < 2; ++mt) {
                    float pa = 0.f, pb = 0.f;
                    #pragma unroll
                    for (int c = 0; c < 8; ++c) {
                        int n = n_base + c * 8 + q2;
                        float b0 = s_b1[n], b1x = s_b1[n + 1];
                        float w0 = s_w2[n], w1x = s_w2[n + 1];
                        pa += fmaxf(acc[mt][c][0] + b0, 0.f) * w0
                            + fmaxf(acc[mt][c][1] + b1x, 0.f) * w1x;
                        pb += fmaxf(acc[mt][c][2] + b0, 0.f) * w0
                            + fmaxf(acc[mt][c][3] + b1x, 0.f) * w1x;
                    }
                    pa += __shfl_xor_sync(0xffffffffu, pa, 1);
                    pa += __shfl_xor_sync(0xffffffffu, pa, 2);
                    pb += __shfl_xor_sync(0xffffffffu, pb, 1);
                    pb += __shfl_xor_sync(0xffffffffu, pb, 2);
                    if ((lid & 3) == 0) {
                        int ra = m_base + mt * 16 + (lid >> 2);
                        red[ra * 2 + nb] = pa;
                        red[(ra + 8) * 2 + nb] = pb;
                    }
                }
                // sync the 4 compute warps, then write 64 outputs
                asm volatile("bar.sync 1, 128;" ::: "memory");
                int li = wg * 32 + lid;
                if (li < 64) {
                    float s = red[li * 2] + red[li * 2 + 1] + b2v;
                    long long po = tc * 64 + li;
                    if (po < P) out[po] = s;
                }
            }
        }
        __syncthreads();
    }
}

extern "C" void kernel_launch(void* const* d_in, const int* in_sizes, int n_in,
                              void* d_out, int out_size) {
    const float* g1  = (const float*)d_in[0];   // graph1_x [N,64]
    const float* g2  = (const float*)d_in[1];   // graph2_x [N,64]
    const int*   il  = (const int*)d_in[2];     // idx_left  [P] int32
    const int*   ir  = (const int*)d_in[3];     // idx_right [P] int32
    const float* W1  = (const float*)d_in[4];   // [128,128]
    const float* b1  = (const float*)d_in[5];   // [128]
    const float* W2  = (const float*)d_in[6];   // [1,128]
    const float* b2  = (const float*)d_in[7];   // [1]
    float*       out = (float*)d_out;           // [P,1]

    int P = in_sizes[2];
    int Nnodes = in_sizes[0] / 64;
    int numTiles = (P + 63) >> 6;
    int grid = numTiles < GRID_CTAS ? numTiles : GRID_CTAS;

    pipnet_prep_wfrag<<<32, 256>>>(W1);

    cudaFuncSetAttribute(pipnet_hmma_kernel,
                         cudaFuncAttributeMaxDynamicSharedMemorySize, SMEM_TOTAL);
    pipnet_hmma_kernel<<<grid, NTHREADS, SMEM_TOTAL>>>(
        g1, g2, il, ir, b1, W2, b2, out, P, Nnodes);
}

// round 15
// speedup vs baseline: 1.8087x; 1.5522x over previous
#include <cuda_runtime.h>
#include <cuda_fp16.h>
#include <cstdint>

// PIPNet fused gather + MLP via mma.sync (HMMA) single-fp16.
//   out[p] = relu(concat(g1[il[p]], g2[ir[p]]) @ W1^T + b1) @ W2^T + b2
//
// R14: R11 structure (MTILE=128, warp 32m x 64n, 2 CTAs/SM) but the CTA-wide
// __syncthreads barriers are replaced by PAIRWISE bar.sync(64): warp pair
// (2w, 2w+1) gathers exactly the 32 A-tile rows it computes (warp 2w: left
// half, warp 2w+1: right half), so producer->consumer is pair-local. The CTA
// becomes 4 independent 64-thread groups -> a straggling gather load stalls
// 2 warps, not 8. (R13's ping-pong idled half the warps and regressed.)

#define MTILE 128
#define NTHREADS 256

// smem layout (bytes): A tile 128x128 fp16 (rows 256B, swizzled 16B chunks).
#define SM_A    0
#define SM_B1   32768
#define SM_W2   33280
#define SM_RED  33792
#define SMEM_TOTAL (33792 + 1024 + 128)

// W1 fp16 fragment buffer: [nb(2)][ks(8)][pr(4)][lane(32)][reg(4)] u32 = 32KB.
__device__ uint32_t g_Wfrag[2 * 8 * 4 * 32 * 4];

static __device__ __forceinline__ uint32_t smem_u32(const void* p) {
    uint32_t a;
    asm("{ .reg .u64 t; cvta.to.shared.u64 t, %1; cvt.u32.u64 %0, t; }"
        : "=r"(a) : "l"(p));
    return a;
}

static __device__ __forceinline__ uint32_t tile_off(int row, int chunk) {
    return (uint32_t)row * 256u + (uint32_t)((chunk ^ (row & 7)) * 16);
}

static __device__ __forceinline__ void ldsm_x4(uint32_t* r, uint32_t addr) {
    asm volatile("ldmatrix.sync.aligned.m8n8.x4.shared.b16 {%0,%1,%2,%3}, [%4];"
                 : "=r"(r[0]), "=r"(r[1]), "=r"(r[2]), "=r"(r[3]) : "r"(addr));
}
static __device__ __forceinline__ void mma_f16(float* c, const uint32_t* a,
                                               uint32_t b0, uint32_t b1) {
    asm volatile("mma.sync.aligned.m16n8k16.row.col.f32.f16.f16.f32 "
                 "{%0,%1,%2,%3}, {%4,%5,%6,%7}, {%8,%9}, {%0,%1,%2,%3};"
                 : "+f"(c[0]), "+f"(c[1]), "+f"(c[2]), "+f"(c[3])
                 : "r"(a[0]), "r"(a[1]), "r"(a[2]), "r"(a[3]), "r"(b0), "r"(b1));
}

static __device__ __forceinline__ uint32_t pack_h2(__half a, __half b) {
    __half2 h = __halves2half2(a, b);
    return *(uint32_t*)&h;
}

// Pairwise named barrier: 2 warps (64 threads), id 1..4 per pair.
static __device__ __forceinline__ void bar_pair(int pair_id) {
    asm volatile("bar.sync %0, 64;" :: "r"(pair_id + 1) : "memory");
}

// ---- Prep: write W1's fp16 mma B-fragments in fragment order ----
// NON-trans ldmatrix x4 reg j at lane l holds the f16x2 pair
// W1h[n][k], W1h[n][k+1] with
//   n = nb*64 + pr*16 + (j>>1)*8 + (l>>2),  k = ks*16 + (j&1)*8 + 2*(l&3).
__global__ void pipnet_prep_wfrag(const float* __restrict__ W1) {
    int flat = blockIdx.x * blockDim.x + threadIdx.x;   // 8192 entries
    if (flat >= 8192) return;
    int j  = flat & 3;
    int l  = (flat >> 2) & 31;
    int pr = (flat >> 7) & 3;
    int ks = (flat >> 9) & 7;
    int nb = (flat >> 12) & 1;
    int n = nb * 64 + pr * 16 + ((j >> 1) << 3) + (l >> 2);
    int k = ks * 16 + ((j & 1) << 3) + 2 * (l & 3);
    g_Wfrag[flat] = pack_h2(__float2half_rn(W1[n * 128 + k]),
                            __float2half_rn(W1[n * 128 + k + 1]));
}

__global__ __launch_bounds__(NTHREADS, 2)
void pipnet_hmma_kernel(const float* __restrict__ g1,
                        const float* __restrict__ g2,
                        const int* __restrict__ idxL,
                        const int* __restrict__ idxR,
                        const float* __restrict__ b1,
                        const float* __restrict__ W2,
                        const float* __restrict__ b2,
                        float* __restrict__ out,
                        int P, int Nnodes)
{
    extern __shared__ char smem[];
    const uint32_t sbase = smem_u32(smem);
    const int tid = threadIdx.x;
    const int wid = tid >> 5;
    const int lid = tid & 31;
    const int w  = wid >> 1;            // pair id (0-3): rows w*32..+31
    const int nb = wid & 1;             // half / n-block within pair
    const long long base = (long long)blockIdx.x * MTILE;

    // ---- Stage b1 / W2 (one-time CTA barrier) ----
    if (tid < 128) {
        *(float*)(smem + SM_B1 + tid * 4) = b1[tid];
        *(float*)(smem + SM_W2 + tid * 4) = W2[tid];
    }
    const float b2v = b2[0];
    __syncthreads();

    // ---- Gather: this warp fills rows w*32..+31, half nb (uniform source) ----
    {
        const int* __restrict__ idx = nb ? idxR : idxL;
        const float* __restrict__ gsrc = nb ? g2 : g1;
        const int lane_in = lid & 15;   // float4 slot within the node row
        #pragma unroll
        for (int i = 0; i < 16; ++i) {
            int r = w * 32 + i * 2 + (lid >> 4);
            long long pair = base + r;
            if (pair >= P) pair = P - 1;
            int srcRow = idx[pair];
            if (srcRow < 0) srcRow = 0;
            if (srcRow >= Nnodes) srcRow = Nnodes - 1;
            const float4* src = (const float4*)(gsrc + (long long)srcRow * 64);
            float4 v = src[lane_in];
            uint2 hv = make_uint2(pack_h2(__float2half_rn(v.x), __float2half_rn(v.y)),
                                  pack_h2(__float2half_rn(v.z), __float2half_rn(v.w)));
            uint32_t off = tile_off(r, nb * 8 + (lane_in >> 1)) + (lane_in & 1) * 8;
            *(uint2*)(smem + SM_A + off) = hv;
        }
    }
    bar_pair(w);   // pair-local: both halves of rows w*32..+31 are in smem

    // ---- HMMA mainloop: warp = 32m x 64n ----
    const int m_base = w * 32;
    const int n_base = nb * 64;
    const int gl = lid & 7;
    const int grp = lid >> 3;

    float acc[2][8][4];
    #pragma unroll
    for (int mt = 0; mt < 2; ++mt)
        #pragma unroll
        for (int c = 0; c < 8; ++c)
            #pragma unroll
            for (int q = 0; q < 4; ++q) acc[mt][c][q] = 0.f;

    const uint32_t aT = sbase + SM_A;
    const uint4* __restrict__ Wf = (const uint4*)g_Wfrag;

    #pragma unroll
    for (int ks = 0; ks < 8; ++ks) {
        int kc = ks * 2;
        uint32_t af0[4], af1[4];
        {
            int row0 = m_base + (grp & 1) * 8 + gl;
            ldsm_x4(af0, aT + tile_off(row0, kc + (grp >> 1)));
            ldsm_x4(af1, aT + tile_off(row0 + 16, kc + (grp >> 1)));
        }
        const uint4* wk = Wf + ((nb * 8 + ks) * 4) * 32 + lid;
        #pragma unroll
        for (int pr = 0; pr < 4; ++pr) {
            uint4 vb = wk[pr * 32];
            mma_f16(acc[0][pr * 2],     af0, vb.x, vb.y);
            mma_f16(acc[0][pr * 2 + 1], af0, vb.z, vb.w);
            mma_f16(acc[1][pr * 2],     af1, vb.x, vb.y);
            mma_f16(acc[1][pr * 2 + 1], af1, vb.z, vb.w);
        }
    }

    // ---- Epilogue: bias + ReLU + W2 dot, quad reduce, pair-local combine ----
    const float* s_b1 = (const float*)(smem + SM_B1);
    const float* s_w2 = (const float*)(smem + SM_W2);
    float* red = (float*)(smem + SM_RED);
    const int q2 = (lid & 3) * 2;

    #pragma unroll
    for (int mt = 0; mt < 2; ++mt) {
        float pa = 0.f, pb = 0.f;   // rows m_base+mt*16+(lid>>2) and +8
        #pragma unroll
        for (int c = 0; c < 8; ++c) {
            int n = n_base + c * 8 + q2;
            float b0 = s_b1[n], b1x = s_b1[n + 1];
            float w0 = s_w2[n], w1x = s_w2[n + 1];
            pa += fmaxf(acc[mt][c][0] + b0, 0.f) * w0
                + fmaxf(acc[mt][c][1] + b1x, 0.f) * w1x;
            pb += fmaxf(acc[mt][c][2] + b0, 0.f) * w0
                + fmaxf(acc[mt][c][3] + b1x, 0.f) * w1x;
        }
        pa += __shfl_xor_sync(0xffffffffu, pa, 1);
        pa += __shfl_xor_sync(0xffffffffu, pa, 2);
        pb += __shfl_xor_sync(0xffffffffu, pb, 1);
        pb += __shfl_xor_sync(0xffffffffu, pb, 2);
        if ((lid & 3) == 0) {
            int ra = m_base + mt * 16 + (lid >> 2);
            red[ra * 2 + nb] = pa;
            red[(ra + 8) * 2 + nb] = pb;
        }
    }
    bar_pair(w);   // pair-local: both n-halves staged for rows w*32..+31

    if (nb == 0) {
        int r = m_base + lid;          // 32 rows, one per lane
        float s = red[r * 2] + red[r * 2 + 1] + b2v;
        long long p = base + r;
        if (p < P) out[p] = s;
    }
}

extern "C" void kernel_launch(void* const* d_in, const int* in_sizes, int n_in,
                              void* d_out, int out_size) {
    const float* g1  = (const float*)d_in[0];   // graph1_x [N,64]
    const float* g2  = (const float*)d_in[1];   // graph2_x [N,64]
    const int*   il  = (const int*)d_in[2];     // idx_left  [P] int32
    const int*   ir  = (const int*)d_in[3];     // idx_right [P] int32
    const float* W1  = (const float*)d_in[4];   // [128,128]
    const float* b1  = (const float*)d_in[5];   // [128]
    const float* W2  = (const float*)d_in[6];   // [1,128]
    const float* b2  = (const float*)d_in[7];   // [1]
    float*       out = (float*)d_out;           // [P,1]

    int P = in_sizes[2];
    int Nnodes = in_sizes[0] / 64;
    int grid = (P + MTILE - 1) / MTILE;

    pipnet_prep_wfrag<<<32, 256>>>(W1);

    cudaFuncSetAttribute(pipnet_hmma_kernel,
                         cudaFuncAttributeMaxDynamicSharedMemorySize, SMEM_TOTAL);
    pipnet_hmma_kernel<<<grid, NTHREADS, SMEM_TOTAL>>>(
        g1, g2, il, ir, b1, W2, b2, out, P, Nnodes);
}